// round 4
// baseline (speedup 1.0000x reference)
#include <cuda_runtime.h>
#include <cuda_bf16.h>
#include <cstdint>

// ===================== constants =====================
#define NTOK   16384
#define DIM    512
#define INV_T  14.285714285714286f   // 1/0.07
#define MARGIN 0.1f

#define KC     64                    // K-chunk (bf16 elems) per pipeline stage
#define NK     (DIM / KC)            // 8 chunks
#define STAGE_BYTES (2 * 128 * KC * 2)   // A tile + B tile per stage = 32KB
#define TILE_BYTES  (128 * KC * 2)       // 16KB each

// ===================== device globals (no cudaMalloc allowed) =====================
__device__ __nv_bfloat16 g_sn[(size_t)NTOK * DIM];
__device__ __nv_bfloat16 g_tn[(size_t)NTOK * DIM];
__device__ double g_sum;

// ===================== helpers =====================
__device__ __forceinline__ uint32_t smem_u32(const void* p) {
    uint32_t a;
    asm("{ .reg .u64 t; cvta.to.shared.u64 t, %1; cvt.u32.u64 %0, t; }" : "=r"(a) : "l"(p));
    return a;
}
__device__ __forceinline__ void cp_async16(uint32_t smem, const void* gmem) {
    asm volatile("cp.async.cg.shared.global [%0], [%1], 16;" :: "r"(smem), "l"(gmem));
}
#define CP_COMMIT() asm volatile("cp.async.commit_group;" ::: "memory")
#define CP_WAIT(n)  asm volatile("cp.async.wait_group %0;" :: "n"(n) : "memory")

__device__ __forceinline__ void ldsm4(uint32_t* r, uint32_t addr) {
    asm volatile("ldmatrix.sync.aligned.m8n8.x4.shared.b16 {%0,%1,%2,%3}, [%4];"
                 : "=r"(r[0]), "=r"(r[1]), "=r"(r[2]), "=r"(r[3]) : "r"(addr));
}
__device__ __forceinline__ void mma16816(float* c, const uint32_t* a, uint32_t b0, uint32_t b1) {
    asm volatile(
        "mma.sync.aligned.m16n8k16.row.col.f32.bf16.bf16.f32 "
        "{%0,%1,%2,%3}, {%4,%5,%6,%7}, {%8,%9}, {%0,%1,%2,%3};"
        : "+f"(c[0]), "+f"(c[1]), "+f"(c[2]), "+f"(c[3])
        : "r"(a[0]), "r"(a[1]), "r"(a[2]), "r"(a[3]), "r"(b0), "r"(b1));
}

// SW128 swizzle: 128B rows -> conflict-free ldmatrix + cp.async stores
#define SWZ(off) ((off) ^ (((off) >> 3) & 0x70))

// ===================== fast softplus (no MUFU) =====================
// softplus(x) = max(x,0) + log1p(exp(-|x|)); FMA/ALU pipes only.
// max abs error ~5e-6 << loss tolerance budget (~6e-4/elem systematic).
__device__ __forceinline__ float softplus_fast(float x) {
    float ax = fminf(fabsf(x), 20.0f);
    float r  = fmaxf(x, 0.0f);
    float t  = ax * -1.4426950408889634f;
    float kf = t + 12582912.0f;                   // rint via magic
    int   sc = __float_as_int(kf) << 23;
    float f  = t - (kf - 12582912.0f);            // f in [-0.5, 0.5]
    float p  = 1.3333558146e-3f;
    p = fmaf(p, f, 9.6181291918e-3f);
    p = fmaf(p, f, 5.5504108664e-2f);
    p = fmaf(p, f, 2.4022650696e-1f);
    p = fmaf(p, f, 6.9314718056e-1f);
    p = fmaf(p, f, 1.0f);
    float e = __int_as_float(__float_as_int(p) + sc);  // exp(-ax) in (2e-9, 1]
    // log1p(e) = 2*atanh(z), z = e/(e+2) in (0, 1/3]
    float d = e + 2.0f;
    float y = fmaf(d, -0.16666667f, 0.83333333f); // ~1/d on [2,3]
    y = y * fmaf(-d, y, 2.0f);                    // Newton 1
    y = y * fmaf(-d, y, 2.0f);                    // Newton 2
    float z  = e * y;
    float z2 = z * z;
    float q  = 0.22222222f;
    q = fmaf(q, z2, 0.28571429f);
    q = fmaf(q, z2, 0.4f);
    q = fmaf(q, z2, 0.66666667f);
    q = fmaf(q, z2, 2.0f);
    return fmaf(z, q, r);
}

// ===================== kernel 1: L2-normalize rows, fp32 -> bf16 =====================
__global__ __launch_bounds__(256) void normalize_kernel(const float* __restrict__ S,
                                                        const float* __restrict__ T) {
    int row = blockIdx.x;
    int tid = threadIdx.x;
    if (row == 0 && tid == 0) g_sum = 0.0;

    const float2* s2 = (const float2*)(S + (size_t)row * DIM);
    const float2* t2 = (const float2*)(T + (size_t)row * DIM);
    float2 sv = s2[tid];
    float2 tv = t2[tid];
    float a = fmaf(sv.x, sv.x, sv.y * sv.y);
    float b = fmaf(tv.x, tv.x, tv.y * tv.y);
    #pragma unroll
    for (int o = 16; o; o >>= 1) {
        a += __shfl_xor_sync(0xffffffffu, a, o);
        b += __shfl_xor_sync(0xffffffffu, b, o);
    }
    __shared__ float sa[8], sb[8];
    int w = tid >> 5, l = tid & 31;
    if (l == 0) { sa[w] = a; sb[w] = b; }
    __syncthreads();
    float ta = 0.f, tb = 0.f;
    #pragma unroll
    for (int i = 0; i < 8; i++) { ta += sa[i]; tb += sb[i]; }
    float ia = rsqrtf(ta);
    float ib = rsqrtf(tb);
    __nv_bfloat162 so = __float22bfloat162_rn(make_float2(sv.x * ia, sv.y * ia));
    __nv_bfloat162 to = __float22bfloat162_rn(make_float2(tv.x * ib, tv.y * ib));
    ((__nv_bfloat162*)g_sn)[(size_t)row * (DIM / 2) + tid] = so;
    ((__nv_bfloat162*)g_tn)[(size_t)row * (DIM / 2) + tid] = to;
}

// ===================== kernel 2: mma.sync GEMM + fused softplus-sum =====================
// CTA tile 128x128, 8 warps (4x2), warp tile 32x64, double-buffered cp.async.
__global__ __launch_bounds__(256, 2) void gemm_loss_kernel() {
    extern __shared__ uint8_t dynsmem[];
    __shared__ float s_red[8];

    int tid  = threadIdx.x;
    int wid  = tid >> 5;
    int lane = tid & 31;

    uint32_t sbase = smem_u32(dynsmem);

    // tile mapping with 8-row bands (L2 locality)
    int bid  = blockIdx.x;
    int band = bid >> 10;            // / (8*128)
    int rem  = bid & 1023;
    int br   = (band << 3) + (rem & 7);
    int bc   = rem >> 3;

    // ---- cp.async setup: per thread 4 A-segs + 4 B-segs of 16B per stage ----
    const uint8_t* gA = (const uint8_t*)g_sn + (size_t)br * 128 * DIM * 2;
    const uint8_t* gB = (const uint8_t*)g_tn + (size_t)bc * 128 * DIM * 2;
    uint32_t soff[4];   // swizzled smem offset within a tile
    uint32_t gofs[4];   // gmem byte offset within a row-block (chunk 0)
    #pragma unroll
    for (int i = 0; i < 4; i++) {
        int idx = tid + (i << 8);        // 0..1023
        int r   = idx >> 3;              // row 0..127
        int sg  = idx & 7;               // 16B segment 0..7
        soff[i] = SWZ((r << 7) + (sg << 4));
        gofs[i] = r * (DIM * 2) + (sg << 4);
    }

    // ---- ldmatrix address components (per lane) ----
    int wm = wid & 3;        // 0..3 along M (rows of 32)
    int wn = wid >> 2;       // 0..1 along N (cols of 64)

    // A: lanes 0-7 m0-7@k0 | 8-15 m8-15@k0 | 16-23 m0-7@k8 | 24-31 m8-15@k8
    int aRow  = (wm << 5) + (lane & 15);
    int aKsel = (lane >> 4) << 4;                 // 0 or 16 bytes
    // B: lanes 0-7 n0-7@k0 | 8-15 n0-7@k8 | 16-23 n8-15@k0 | 24-31 n8-15@k8
    int bRow  = (wn << 6) + (lane & 7) + ((lane & 16) >> 1);
    int bKsel = (lane & 8) << 1;                  // 0 or 16 bytes

    float acc[64];
    #pragma unroll
    for (int i = 0; i < 64; i++) acc[i] = 0.f;

    // ---- prologue: stage 0 ----
    {
        uint32_t sA = sbase, sB = sbase + TILE_BYTES;
        #pragma unroll
        for (int i = 0; i < 4; i++) cp_async16(sA + soff[i], gA + gofs[i]);
        #pragma unroll
        for (int i = 0; i < 4; i++) cp_async16(sB + soff[i], gB + gofs[i]);
        CP_COMMIT();
    }

    // ---- mainloop ----
    for (int c = 0; c < NK; ++c) {
        if (c + 1 < NK) {
            uint32_t st = (uint32_t)((c + 1) & 1) * STAGE_BYTES;
            uint32_t sA = sbase + st, sB = sA + TILE_BYTES;
            uint32_t gk = (uint32_t)(c + 1) * (KC * 2);
            #pragma unroll
            for (int i = 0; i < 4; i++) cp_async16(sA + soff[i], gA + gofs[i] + gk);
            #pragma unroll
            for (int i = 0; i < 4; i++) cp_async16(sB + soff[i], gB + gofs[i] + gk);
            CP_COMMIT();
            CP_WAIT(1);
        } else {
            CP_WAIT(0);
        }
        __syncthreads();

        uint32_t aBase = sbase + (uint32_t)(c & 1) * STAGE_BYTES;
        uint32_t bBase = aBase + TILE_BYTES;

        #pragma unroll
        for (int ks = 0; ks < KC / 16; ++ks) {
            uint32_t a[2][4];
            #pragma unroll
            for (int mi = 0; mi < 2; ++mi) {
                int row = aRow + (mi << 4);
                uint32_t kb = (uint32_t)(aKsel + (ks << 5));
                ldsm4(a[mi], aBase + (row << 7) + (kb ^ ((row & 7) << 4)));
            }
            #pragma unroll
            for (int nb = 0; nb < 4; ++nb) {
                uint32_t b[4];
                int row = bRow + (nb << 4);
                uint32_t kb = (uint32_t)(bKsel + (ks << 5));
                ldsm4(b, bBase + (row << 7) + (kb ^ ((row & 7) << 4)));
                #pragma unroll
                for (int mi = 0; mi < 2; ++mi) {
                    mma16816(&acc[((mi << 3) + (nb << 1)) << 2],       a[mi], b[0], b[1]);
                    mma16816(&acc[((mi << 3) + (nb << 1) + 1) << 2],   a[mi], b[2], b[3]);
                }
            }
        }
        __syncthreads();
    }

    // ---- fused epilogue: softplus + sum ----
    int gid  = lane >> 2;           // groupID (row within m8)
    int tg   = lane & 3;
    int growb = (br << 7) + (wm << 5);
    int gcolb = (bc << 7) + (wn << 6) + (tg << 1);

    float sum = 0.f;
    #pragma unroll
    for (int mi = 0; mi < 2; ++mi) {
        #pragma unroll
        for (int ni = 0; ni < 8; ++ni) {
            const float* cf = &acc[((mi << 3) + ni) << 2];
            int r0 = growb + (mi << 4) + gid;
            int c0 = gcolb + (ni << 3);
            #pragma unroll
            for (int e = 0; e < 4; ++e) {
                int row = r0 + ((e >> 1) << 3);   // +8 for c2/c3
                int col = c0 + (e & 1);
                float l = cf[e] * INV_T;
                float x = (row == col) ? (-l - MARGIN) : (l - MARGIN);
                sum += softplus_fast(x);
            }
        }
    }

    // block reduce -> global double accumulator
    #pragma unroll
    for (int o = 16; o; o >>= 1) sum += __shfl_xor_sync(0xffffffffu, sum, o);
    if (lane == 0) s_red[wid] = sum;
    __syncthreads();
    if (tid == 0) {
        float s = 0.f;
        #pragma unroll
        for (int i = 0; i < 8; i++) s += s_red[i];
        atomicAdd(&g_sum, (double)s);
    }
}

// ===================== kernel 3: finalize =====================
__global__ void finalize_kernel(float* out) {
    out[0] = (float)(g_sum * (1.0 / (double)NTOK));
}

// ===================== launch =====================
extern "C" void kernel_launch(void* const* d_in, const int* in_sizes, int n_in,
                              void* d_out, int out_size) {
    const float* S = (const float*)d_in[0];
    const float* T = (const float*)d_in[1];
    cudaFuncSetAttribute(gemm_loss_kernel,
                         cudaFuncAttributeMaxDynamicSharedMemorySize, 2 * STAGE_BYTES);
    normalize_kernel<<<NTOK, 256>>>(S, T);
    gemm_loss_kernel<<<(NTOK / 128) * (NTOK / 128), 256, 2 * STAGE_BYTES>>>();
    finalize_kernel<<<1, 1>>>((float*)d_out);
}